// round 1
// baseline (speedup 1.0000x reference)
#include <cuda_runtime.h>
#include <math.h>

#define HDIM 512
#define NPT  4095          // nodes per tree (2*2048-1)
#define NB   8             // batch of trees
#define NTOT (NPT*NB)      // 32760
#define MAXL 16384         // max nodes in any layer (leaf layer)

// ---------------- device scratch (static globals: no allocs allowed) ----------------
__device__ float g_h [(size_t)NTOT*HDIM];   // bottom-up states
__device__ float g_hd[(size_t)NTOT*HDIM];   // top-down states
__device__ float g_S [(size_t)MAXL*1536];   // per-layer pre-activations: [z | r | th]
__device__ float g_V [(size_t)MAXL*HDIM];   // r * h_gate

__device__ __forceinline__ float sigf(float x){ return 1.f/(1.f+expf(-x)); }

// ---------------- generic fused-gather GEMM ----------------
// C[M x N] (+)= gatherA[M x 512] @ W^T (+ bias). N = 512*nseg (nseg<=3), each
// 512-column segment uses its own weight/bias pointer.
// A gather modes:
//   0: row m -> node (tree*NPT + a_start + pos)             (feat gather)
//   1: row m -> h[c0]+h[c0+1], c0 = tree*NPT+a_start+2*pos  (children pair-sum)
//   2: row m -> base[tree*NPT + a_start + (pos>>1)]         (father repeat)
//   3: row m -> base[m]                                     (plain)
// asel: 0=feat param, 1=g_h, 2=g_hd, 3=g_V.  csel: 0=g_S, 1=Cout param.
__global__ __launch_bounds__(256)
void gemm_k(const float* __restrict__ feat, int asel,
            const float* __restrict__ W0, const float* __restrict__ W1p, const float* __restrict__ W2p,
            const float* __restrict__ B0, const float* __restrict__ B1p, const float* __restrict__ B2p,
            float* __restrict__ Cout, int csel, int ldc, int ccol,
            int M, int mode, int ptlog, int a_start, int accum)
{
    const float* Abase = (asel==0)?feat : (asel==1)?g_h : (asel==2)?g_hd : g_V;
    float* C = (csel==0) ? g_S : Cout;

    __shared__ __align__(16) float As[16][64];
    __shared__ __align__(16) float Bs[16][64];

    const int tid = threadIdx.x;
    const int m0  = blockIdx.y << 6;
    const int n0  = blockIdx.x << 6;
    const int seg = n0 >> 9;
    const float* W    = (seg==0)?W0:(seg==1)?W1p:W2p;
    const float* bias = (seg==0)?B0:(seg==1)?B1p:B2p;
    const int nloc0 = n0 & 511;

    const int lr = tid & 63;          // row within tile (A: m, B: n)
    const int lk = (tid >> 6) << 2;   // 4 consecutive k per thread

    // resolve A-row pointer(s) once
    const float* arow  = 0;
    const float* arow2 = 0;
    {
        int r = m0 + lr;
        if (r < M) {
            if (mode == 3) {
                arow = Abase + (size_t)r * HDIM;
            } else {
                int tree = r >> ptlog;
                int pos  = r & ((1 << ptlog) - 1);
                if (mode == 0) {
                    arow = Abase + (size_t)(tree*NPT + a_start + pos) * HDIM;
                } else if (mode == 1) {
                    int c0 = tree*NPT + a_start + (pos << 1);
                    arow  = Abase + (size_t)c0 * HDIM;
                    arow2 = arow + HDIM;
                } else {
                    int f = tree*NPT + a_start + (pos >> 1);
                    arow = Abase + (size_t)f * HDIM;
                }
            }
        }
    }
    const float* wrow = W + (size_t)(nloc0 + lr) * HDIM;

    float acc[4][4];
    #pragma unroll
    for (int i=0;i<4;i++)
        #pragma unroll
        for (int j=0;j<4;j++) acc[i][j] = 0.f;

    const int ty = tid >> 4;   // 0..15
    const int tx = tid & 15;   // 0..15

    for (int kt = 0; kt < HDIM; kt += 16) {
        float4 av = make_float4(0.f,0.f,0.f,0.f);
        if (arow) {
            av = *(const float4*)(arow + kt + lk);
            if (arow2) {
                float4 t2 = *(const float4*)(arow2 + kt + lk);
                av.x += t2.x; av.y += t2.y; av.z += t2.z; av.w += t2.w;
            }
        }
        float4 bv = *(const float4*)(wrow + kt + lk);

        As[lk+0][lr]=av.x; As[lk+1][lr]=av.y; As[lk+2][lr]=av.z; As[lk+3][lr]=av.w;
        Bs[lk+0][lr]=bv.x; Bs[lk+1][lr]=bv.y; Bs[lk+2][lr]=bv.z; Bs[lk+3][lr]=bv.w;
        __syncthreads();

        #pragma unroll
        for (int k=0;k<16;k++) {
            float4 a = *(const float4*)&As[k][ty<<2];
            float4 b = *(const float4*)&Bs[k][tx<<2];
            acc[0][0]+=a.x*b.x; acc[0][1]+=a.x*b.y; acc[0][2]+=a.x*b.z; acc[0][3]+=a.x*b.w;
            acc[1][0]+=a.y*b.x; acc[1][1]+=a.y*b.y; acc[1][2]+=a.y*b.z; acc[1][3]+=a.y*b.w;
            acc[2][0]+=a.z*b.x; acc[2][1]+=a.z*b.y; acc[2][2]+=a.z*b.z; acc[2][3]+=a.z*b.w;
            acc[3][0]+=a.w*b.x; acc[3][1]+=a.w*b.y; acc[3][2]+=a.w*b.z; acc[3][3]+=a.w*b.w;
        }
        __syncthreads();
    }

    #pragma unroll
    for (int i=0;i<4;i++) {
        int rr = m0 + (ty<<2) + i;
        if (rr >= M) continue;
        float* crow = C + (size_t)rr*ldc + ccol + n0 + (tx<<2);
        #pragma unroll
        for (int j=0;j<4;j++) {
            float v = acc[i][j];
            if (bias)  v += bias[nloc0 + (tx<<2) + j];
            if (accum) v += crow[j];
            crow[j] = v;
        }
    }
}

// ---------------- elementwise epilogues ----------------
__global__ void leaf_epi(int M, int ptlog)
{
    int idx = blockIdx.x*256 + threadIdx.x;
    if (idx >= M*HDIM) return;
    int m = idx >> 9, k = idx & 511;
    int tree = m >> ptlog, pos = m & ((1<<ptlog)-1);
    float z  = sigf(g_S[(size_t)m*1536 + k]);
    float th = g_S[(size_t)m*1536 + 512 + k];
    int g = tree*NPT + pos;   // leaves start at 0
    g_h[(size_t)g*HDIM + k] = (1.f - z) * tanhf(th);
}

__global__ void bu_e1(int M, int ptlog, int son_start)
{
    int idx = blockIdx.x*256 + threadIdx.x;
    if (idx >= M*HDIM) return;
    int m = idx >> 9, k = idx & 511;
    int tree = m >> ptlog, pos = m & ((1<<ptlog)-1);
    size_t c0 = (size_t)(tree*NPT + son_start + (pos<<1))*HDIM + k;
    float hs = g_h[c0] + g_h[c0 + HDIM];
    float z  = sigf(g_S[(size_t)m*1536 + k]);
    float r  = sigf(g_S[(size_t)m*1536 + 512 + k]);
    g_S[(size_t)m*1536 + k] = z;
    g_V[(size_t)m*HDIM + k] = r * hs;
}

__global__ void bu_e2(int M, int ptlog, int son_start, int fa_start)
{
    int idx = blockIdx.x*256 + threadIdx.x;
    if (idx >= M*HDIM) return;
    int m = idx >> 9, k = idx & 511;
    int tree = m >> ptlog, pos = m & ((1<<ptlog)-1);
    size_t c0 = (size_t)(tree*NPT + son_start + (pos<<1))*HDIM + k;
    float hs   = g_h[c0] + g_h[c0 + HDIM];
    float z    = g_S[(size_t)m*1536 + k];
    float cand = tanhf(g_S[(size_t)m*1536 + 1024 + k]);
    int g = tree*NPT + fa_start + pos;
    g_h[(size_t)g*HDIM + k] = z*hs + (1.f - z)*cand;
}

__global__ void td_e1(int M, int ptlog, int fa_start)
{
    int idx = blockIdx.x*256 + threadIdx.x;
    if (idx >= M*HDIM) return;
    int m = idx >> 9, k = idx & 511;
    int tree = m >> ptlog, pos = m & ((1<<ptlog)-1);
    int f = tree*NPT + fa_start + (pos >> 1);
    float hf = g_hd[(size_t)f*HDIM + k];
    float z  = sigf(g_S[(size_t)m*1536 + k]);
    float r  = sigf(g_S[(size_t)m*1536 + 512 + k]);
    g_S[(size_t)m*1536 + k] = z;
    g_V[(size_t)m*HDIM + k] = r * hf;
}

__global__ void td_e2(int M, int ptlog, int fa_start, int son_start)
{
    int idx = blockIdx.x*256 + threadIdx.x;
    if (idx >= M*HDIM) return;
    int m = idx >> 9, k = idx & 511;
    int tree = m >> ptlog, pos = m & ((1<<ptlog)-1);
    int f = tree*NPT + fa_start + (pos >> 1);
    float hf   = g_hd[(size_t)f*HDIM + k];
    float z    = g_S[(size_t)m*1536 + k];
    float cand = tanhf(g_S[(size_t)m*1536 + 1024 + k]);
    int g = tree*NPT + son_start + pos;
    g_hd[(size_t)g*HDIM + k] = z*hf + (1.f - z)*cand;
}

__global__ void root_copy()
{
    int idx = blockIdx.x*256 + threadIdx.x;
    if (idx >= NB*HDIM) return;
    int tree = idx >> 9, k = idx & 511;
    size_t g = (size_t)(tree*NPT + (NPT-1))*HDIM + k;
    g_hd[g] = g_h[g];
}

// ---------------- host orchestration ----------------
extern "C" void kernel_launch(void* const* d_in, const int* in_sizes, int n_in,
                              void* d_out, int out_size)
{
    (void)in_sizes; (void)n_in; (void)out_size;
    const float* feat = (const float*)d_in[0];
    const float* Wh   = (const float*)d_in[1];
    const float* Wz   = (const float*)d_in[2];
    const float* Wr   = (const float*)d_in[3];
    const float* Uh   = (const float*)d_in[4];
    const float* Uz   = (const float*)d_in[5];
    const float* bUz  = (const float*)d_in[6];
    const float* Ur   = (const float*)d_in[7];
    const float* bUr  = (const float*)d_in[8];
    const float* Whd  = (const float*)d_in[9];
    const float* Wzd  = (const float*)d_in[10];
    const float* Wrd  = (const float*)d_in[11];
    const float* Uhd  = (const float*)d_in[12];
    const float* Uzd  = (const float*)d_in[13];
    const float* bUzd = (const float*)d_in[14];
    const float* Urd  = (const float*)d_in[15];
    const float* bUrd = (const float*)d_in[16];
    const float* W1   = (const float*)d_in[17];
    const float* b1   = (const float*)d_in[18];
    const float* W2   = (const float*)d_in[19];
    const float* b2   = (const float*)d_in[20];
    float* out = (float*)d_out;

    // level layout per tree (bottom-up node numbering)
    static const int LS[12] = {0,2048,3072,3584,3840,3968,4032,4064,4080,4088,4092,4094};
    static const int LG[12] = {11,10,9,8,7,6,5,4,3,2,1,0};   // log2(level size)

    auto gemm = [&](int asel,
                    const float* w0, const float* w1, const float* w2,
                    const float* a0, const float* a1, const float* a2,
                    int csel, float* cptr, int ldc, int ccol,
                    int M, int N, int mode, int ptlog, int a_start, int accum)
    {
        dim3 grid(N/64, (M+63)/64);
        gemm_k<<<grid, 256>>>(feat, asel, w0, w1, w2, a0, a1, a2,
                              cptr, csel, ldc, ccol, M, mode, ptlog, a_start, accum);
    };

    // ---- leaves: h = (1 - sig(Wz x)) * tanh(Wh x)  (no biases) ----
    {
        int M = NB * 2048;
        gemm(0, Wz, Wh, nullptr, nullptr, nullptr, nullptr,
             0, nullptr, 1536, 0, M, 1024, /*mode*/0, /*ptlog*/11, /*a_start*/0, 0);
        leaf_epi<<<(M*HDIM + 255)/256, 256>>>(M, 11);
    }

    // ---- bottom-up layers ----
    for (int l = 0; l < 11; l++) {
        int M   = NB << LG[l+1];
        int lg  = LG[l+1];
        int sst = LS[l], fst = LS[l+1];
        // S[:,0:1536] = X @ [Wz;Wr;Wh]^T + [bUz;bUr;0]
        gemm(0, Wz, Wr, Wh, bUz, bUr, nullptr, 0, nullptr, 1536, 0, M, 1536, 0, lg, fst, 0);
        // S[:,0:1024] += HS @ [Uz;Ur]^T    (HS = pair-sum of children)
        gemm(1, Uz, Ur, nullptr, nullptr, nullptr, nullptr, 0, nullptr, 1536, 0, M, 1024, 1, lg, sst, 1);
        bu_e1<<<(M*HDIM + 255)/256, 256>>>(M, lg, sst);
        // S[:,1024:1536] += V @ Uh^T
        gemm(3, Uh, nullptr, nullptr, nullptr, nullptr, nullptr, 0, nullptr, 1536, 1024, M, 512, 3, lg, 0, 1);
        bu_e2<<<(M*HDIM + 255)/256, 256>>>(M, lg, sst, fst);
    }

    root_copy<<<(NB*HDIM + 255)/256, 256>>>();

    // ---- top-down layers ----
    for (int l = 10; l >= 0; l--) {
        int M   = NB << LG[l];
        int lg  = LG[l];
        int sst = LS[l], fst = LS[l+1];
        gemm(0, Wzd, Wrd, Whd, bUzd, bUrd, nullptr, 0, nullptr, 1536, 0, M, 1536, 0, lg, sst, 0);
        gemm(2, Uzd, Urd, nullptr, nullptr, nullptr, nullptr, 0, nullptr, 1536, 0, M, 1024, 2, lg, fst, 1);
        td_e1<<<(M*HDIM + 255)/256, 256>>>(M, lg, fst);
        gemm(3, Uhd, nullptr, nullptr, nullptr, nullptr, nullptr, 0, nullptr, 1536, 1024, M, 512, 3, lg, 0, 1);
        td_e2<<<(M*HDIM + 255)/256, 256>>>(M, lg, fst, sst);
    }

    // ---- output: out = h @ W1^T + b1 + hd @ W2^T + b2 ----
    {
        int M = NTOT;
        gemm(1, W1, nullptr, nullptr, b1, nullptr, nullptr, 1, out, 512, 0, M, 512, 3, 0, 0, 0);
        gemm(2, W2, nullptr, nullptr, b2, nullptr, nullptr, 1, out, 512, 0, M, 512, 3, 0, 0, 1);
    }
}

// round 2
// speedup vs baseline: 1.6499x; 1.6499x over previous
#include <cuda_runtime.h>
#include <cuda_bf16.h>
#include <math.h>
#include <stdint.h>

#define HDIM 512
#define NPT  4095          // nodes per tree (2*2048-1)
#define NB   8             // batch of trees
#define NTOT (NPT*NB)      // 32760
#define MAXL 16384         // max nodes in any layer

// ---------------- device scratch ----------------
__device__ float g_h [(size_t)NTOT*HDIM];
__device__ float g_hd[(size_t)NTOT*HDIM];
__device__ float g_S [(size_t)MAXL*1536];
__device__ float g_V [(size_t)MAXL*HDIM];

#define WMAT_ELEMS (512*512)
// 14 weight matrices pre-split into bf16 hi/lo
__device__ __nv_bfloat16 g_Whi[(size_t)14*WMAT_ELEMS];
__device__ __nv_bfloat16 g_Wlo[(size_t)14*WMAT_ELEMS];

__device__ __forceinline__ float sigf(float x){ return 1.f/(1.f+expf(-x)); }

// ---------------- weight split ----------------
__global__ void split_w(const float* __restrict__ src, int slot)
{
    int idx = blockIdx.x*256 + threadIdx.x;   // grid covers WMAT_ELEMS
    float x = src[idx];
    __nv_bfloat16 h = __float2bfloat16(x);
    float r = x - __bfloat162float(h);
    g_Whi[(size_t)slot*WMAT_ELEMS + idx] = h;
    g_Wlo[(size_t)slot*WMAT_ELEMS + idx] = __float2bfloat16(r);
}

// ---------------- bf16 split tensor-core GEMM ----------------
// C[M x N] (+)= gatherA[M x 512] @ W^T (+bias), N = 512*nseg, per-segment W/bias.
// A gather modes: 0 feat-node, 1 children pair-sum, 2 father-repeat, 3 plain.
// asel: 0=feat, 1=g_h, 2=g_hd, 3=g_V.  csel: 0=g_S, 1=Cout.
#define MMA_BF16(d, a, b) asm volatile( \
  "mma.sync.aligned.m16n8k16.row.col.f32.bf16.bf16.f32 " \
  "{%0,%1,%2,%3}, {%4,%5,%6,%7}, {%8,%9}, {%0,%1,%2,%3};\n" \
  : "+f"(d[0]),"+f"(d[1]),"+f"(d[2]),"+f"(d[3]) \
  : "r"(a[0]),"r"(a[1]),"r"(a[2]),"r"(a[3]), "r"(b[0]),"r"(b[1]))

__global__ __launch_bounds__(128)
void mma_gemm(const float* __restrict__ feat, int asel,
              int w0, int w1, int w2,
              const float* __restrict__ B0, const float* __restrict__ B1, const float* __restrict__ B2,
              float* __restrict__ Cout, int csel, int ldc, int ccol,
              int M, int mode, int ptlog, int a_start, int accum)
{
    const float* Abase = (asel==0)?feat : (asel==1)?g_h : (asel==2)?g_hd : g_V;
    float* C = (csel==0) ? g_S : Cout;

    // 64x64 tile, BK=32. stride 20 words (80B) -> conflict-free fragment LDS
    __shared__ uint32_t Ah[64][20], Al[64][20], Bh[64][20], Bl[64][20];

    const int t   = threadIdx.x;
    const int m0  = blockIdx.y << 6;
    const int n0  = blockIdx.x << 6;
    const int seg = n0 >> 9;
    const int wIdx = (seg==0)?w0:(seg==1)?w1:w2;
    const float* bias = (seg==0)?B0:(seg==1)?B1:B2;
    const int nloc0 = n0 & 511;

    const int rbase = t >> 3;     // 0..15
    const int c4    = t & 7;      // float4 / uint2 chunk within 32-wide k-tile

    // resolve A row pointers once (4 rows per thread)
    const float* ap [4];
    const float* ap2[4];
    #pragma unroll
    for (int i=0;i<4;i++) {
        ap[i]=nullptr; ap2[i]=nullptr;
        int r = m0 + rbase + 16*i;
        if (r < M) {
            if (mode==3) ap[i] = Abase + (size_t)r*HDIM;
            else {
                int tree = r >> ptlog;
                int pos  = r & ((1<<ptlog)-1);
                if (mode==0) ap[i] = Abase + (size_t)(tree*NPT + a_start + pos)*HDIM;
                else if (mode==1) {
                    int c0i = tree*NPT + a_start + (pos<<1);
                    ap[i]  = Abase + (size_t)c0i*HDIM;
                    ap2[i] = ap[i] + HDIM;
                } else {
                    int f = tree*NPT + a_start + (pos>>1);
                    ap[i] = Abase + (size_t)f*HDIM;
                }
            }
        }
    }
    const __nv_bfloat16* wb_hi = g_Whi + (size_t)wIdx*WMAT_ELEMS;
    const __nv_bfloat16* wb_lo = g_Wlo + (size_t)wIdx*WMAT_ELEMS;

    const int L   = t & 31;
    const int wid = t >> 5;
    const int wm  = (wid >> 1) * 32;
    const int wn  = (wid &  1) * 32;

    float acc[2][4][4];
    #pragma unroll
    for (int a=0;a<2;a++)
      #pragma unroll
      for (int b=0;b<4;b++)
        #pragma unroll
        for (int c=0;c<4;c++) acc[a][b][c]=0.f;

    for (int kt = 0; kt < HDIM; kt += 32) {
        // ---- A: fp32 gather (+pair-sum) -> split to bf16 hi/lo ----
        #pragma unroll
        for (int i=0;i<4;i++) {
            float4 v = make_float4(0.f,0.f,0.f,0.f);
            if (ap[i]) {
                v = *(const float4*)(ap[i] + kt + c4*4);
                if (ap2[i]) {
                    float4 u = *(const float4*)(ap2[i] + kt + c4*4);
                    v.x+=u.x; v.y+=u.y; v.z+=u.z; v.w+=u.w;
                }
            }
            __nv_bfloat16 hx=__float2bfloat16(v.x), hy=__float2bfloat16(v.y),
                          hz=__float2bfloat16(v.z), hw=__float2bfloat16(v.w);
            float rx=v.x-__bfloat162float(hx), ry=v.y-__bfloat162float(hy),
                  rz=v.z-__bfloat162float(hz), rw=v.w-__bfloat162float(hw);
            __nv_bfloat16 lx=__float2bfloat16(rx), ly=__float2bfloat16(ry),
                          lz=__float2bfloat16(rz), lw=__float2bfloat16(rw);
            uint32_t h0 = ((uint32_t)__bfloat16_as_ushort(hy)<<16) | __bfloat16_as_ushort(hx);
            uint32_t h1 = ((uint32_t)__bfloat16_as_ushort(hw)<<16) | __bfloat16_as_ushort(hz);
            uint32_t l0 = ((uint32_t)__bfloat16_as_ushort(ly)<<16) | __bfloat16_as_ushort(lx);
            uint32_t l1 = ((uint32_t)__bfloat16_as_ushort(lw)<<16) | __bfloat16_as_ushort(lz);
            int row = rbase + 16*i;
            Ah[row][c4*2]=h0; Ah[row][c4*2+1]=h1;
            Al[row][c4*2]=l0; Al[row][c4*2+1]=l1;
        }
        // ---- B: copy pre-split bf16 ----
        #pragma unroll
        for (int i=0;i<4;i++) {
            int row = rbase + 16*i;
            size_t off = (size_t)(nloc0 + row)*HDIM + kt + c4*4;
            uint2 vh = *(const uint2*)(wb_hi + off);
            uint2 vl = *(const uint2*)(wb_lo + off);
            Bh[row][c4*2]=vh.x; Bh[row][c4*2+1]=vh.y;
            Bl[row][c4*2]=vl.x; Bl[row][c4*2+1]=vl.y;
        }
        __syncthreads();

        #pragma unroll
        for (int ks=0; ks<2; ks++) {
            const int kw = ks*8;
            uint32_t ah[2][4], al[2][4];
            #pragma unroll
            for (int mt=0; mt<2; mt++) {
                int rA = wm + mt*16 + (L>>2);
                int cA = kw + (L&3);
                ah[mt][0]=Ah[rA][cA];   ah[mt][1]=Ah[rA+8][cA];
                ah[mt][2]=Ah[rA][cA+4]; ah[mt][3]=Ah[rA+8][cA+4];
                al[mt][0]=Al[rA][cA];   al[mt][1]=Al[rA+8][cA];
                al[mt][2]=Al[rA][cA+4]; al[mt][3]=Al[rA+8][cA+4];
            }
            uint32_t bh[4][2], bl[4][2];
            #pragma unroll
            for (int nt=0; nt<4; nt++) {
                int rB = wn + nt*8 + (L>>2);
                int cB = kw + (L&3);
                bh[nt][0]=Bh[rB][cB]; bh[nt][1]=Bh[rB][cB+4];
                bl[nt][0]=Bl[rB][cB]; bl[nt][1]=Bl[rB][cB+4];
            }
            #pragma unroll
            for (int mt=0;mt<2;mt++)
              #pragma unroll
              for (int nt=0;nt<4;nt++) {
                MMA_BF16(acc[mt][nt], ah[mt], bh[nt]);
                MMA_BF16(acc[mt][nt], ah[mt], bl[nt]);
                MMA_BF16(acc[mt][nt], al[mt], bh[nt]);
              }
        }
        __syncthreads();
    }

    // ---- epilogue ----
    #pragma unroll
    for (int mt=0;mt<2;mt++) {
        int r0 = m0 + wm + mt*16 + (L>>2);
        #pragma unroll
        for (int nt=0;nt<4;nt++) {
            int ccl = wn + nt*8 + 2*(L&3);   // col within 64-tile
            float b0=0.f, b1=0.f;
            if (bias) { b0 = bias[nloc0+ccl]; b1 = bias[nloc0+ccl+1]; }
            if (r0 < M) {
                float* p = C + (size_t)r0*ldc + ccol + n0 + ccl;
                float v0 = acc[mt][nt][0] + b0, v1 = acc[mt][nt][1] + b1;
                if (accum){ v0+=p[0]; v1+=p[1]; }
                p[0]=v0; p[1]=v1;
            }
            int r1 = r0 + 8;
            if (r1 < M) {
                float* p = C + (size_t)r1*ldc + ccol + n0 + ccl;
                float v0 = acc[mt][nt][2] + b0, v1 = acc[mt][nt][3] + b1;
                if (accum){ v0+=p[0]; v1+=p[1]; }
                p[0]=v0; p[1]=v1;
            }
        }
    }
}

// ---------------- elementwise epilogues (unchanged) ----------------
__global__ void leaf_epi(int M, int ptlog)
{
    int idx = blockIdx.x*256 + threadIdx.x;
    if (idx >= M*HDIM) return;
    int m = idx >> 9, k = idx & 511;
    int tree = m >> ptlog, pos = m & ((1<<ptlog)-1);
    float z  = sigf(g_S[(size_t)m*1536 + k]);
    float th = g_S[(size_t)m*1536 + 512 + k];
    int g = tree*NPT + pos;
    g_h[(size_t)g*HDIM + k] = (1.f - z) * tanhf(th);
}

__global__ void bu_e1(int M, int ptlog, int son_start)
{
    int idx = blockIdx.x*256 + threadIdx.x;
    if (idx >= M*HDIM) return;
    int m = idx >> 9, k = idx & 511;
    int tree = m >> ptlog, pos = m & ((1<<ptlog)-1);
    size_t c0 = (size_t)(tree*NPT + son_start + (pos<<1))*HDIM + k;
    float hs = g_h[c0] + g_h[c0 + HDIM];
    float z  = sigf(g_S[(size_t)m*1536 + k]);
    float r  = sigf(g_S[(size_t)m*1536 + 512 + k]);
    g_S[(size_t)m*1536 + k] = z;
    g_V[(size_t)m*HDIM + k] = r * hs;
}

__global__ void bu_e2(int M, int ptlog, int son_start, int fa_start)
{
    int idx = blockIdx.x*256 + threadIdx.x;
    if (idx >= M*HDIM) return;
    int m = idx >> 9, k = idx & 511;
    int tree = m >> ptlog, pos = m & ((1<<ptlog)-1);
    size_t c0 = (size_t)(tree*NPT + son_start + (pos<<1))*HDIM + k;
    float hs   = g_h[c0] + g_h[c0 + HDIM];
    float z    = g_S[(size_t)m*1536 + k];
    float cand = tanhf(g_S[(size_t)m*1536 + 1024 + k]);
    int g = tree*NPT + fa_start + pos;
    g_h[(size_t)g*HDIM + k] = z*hs + (1.f - z)*cand;
}

__global__ void td_e1(int M, int ptlog, int fa_start)
{
    int idx = blockIdx.x*256 + threadIdx.x;
    if (idx >= M*HDIM) return;
    int m = idx >> 9, k = idx & 511;
    int tree = m >> ptlog, pos = m & ((1<<ptlog)-1);
    int f = tree*NPT + fa_start + (pos >> 1);
    float hf = g_hd[(size_t)f*HDIM + k];
    float z  = sigf(g_S[(size_t)m*1536 + k]);
    float r  = sigf(g_S[(size_t)m*1536 + 512 + k]);
    g_S[(size_t)m*1536 + k] = z;
    g_V[(size_t)m*HDIM + k] = r * hf;
}

__global__ void td_e2(int M, int ptlog, int fa_start, int son_start)
{
    int idx = blockIdx.x*256 + threadIdx.x;
    if (idx >= M*HDIM) return;
    int m = idx >> 9, k = idx & 511;
    int tree = m >> ptlog, pos = m & ((1<<ptlog)-1);
    int f = tree*NPT + fa_start + (pos >> 1);
    float hf   = g_hd[(size_t)f*HDIM + k];
    float z    = g_S[(size_t)m*1536 + k];
    float cand = tanhf(g_S[(size_t)m*1536 + 1024 + k]);
    int g = tree*NPT + son_start + pos;
    g_hd[(size_t)g*HDIM + k] = z*hf + (1.f - z)*cand;
}

__global__ void root_copy()
{
    int idx = blockIdx.x*256 + threadIdx.x;
    if (idx >= NB*HDIM) return;
    int tree = idx >> 9, k = idx & 511;
    size_t g = (size_t)(tree*NPT + (NPT-1))*HDIM + k;
    g_hd[g] = g_h[g];
}

// ---------------- host orchestration ----------------
// weight slot ids
#define W_WH 0
#define W_WZ 1
#define W_WR 2
#define W_UH 3
#define W_UZ 4
#define W_UR 5
#define W_WHD 6
#define W_WZD 7
#define W_WRD 8
#define W_UHD 9
#define W_UZD 10
#define W_URD 11
#define W_W1 12
#define W_W2 13

extern "C" void kernel_launch(void* const* d_in, const int* in_sizes, int n_in,
                              void* d_out, int out_size)
{
    (void)in_sizes; (void)n_in; (void)out_size;
    const float* feat = (const float*)d_in[0];
    const float* Wh   = (const float*)d_in[1];
    const float* Wz   = (const float*)d_in[2];
    const float* Wr   = (const float*)d_in[3];
    const float* Uh   = (const float*)d_in[4];
    const float* Uz   = (const float*)d_in[5];
    const float* bUz  = (const float*)d_in[6];
    const float* Ur   = (const float*)d_in[7];
    const float* bUr  = (const float*)d_in[8];
    const float* Whd  = (const float*)d_in[9];
    const float* Wzd  = (const float*)d_in[10];
    const float* Wrd  = (const float*)d_in[11];
    const float* Uhd  = (const float*)d_in[12];
    const float* Uzd  = (const float*)d_in[13];
    const float* bUzd = (const float*)d_in[14];
    const float* Urd  = (const float*)d_in[15];
    const float* bUrd = (const float*)d_in[16];
    const float* W1   = (const float*)d_in[17];
    const float* b1   = (const float*)d_in[18];
    const float* W2   = (const float*)d_in[19];
    const float* b2   = (const float*)d_in[20];
    float* out = (float*)d_out;

    // pre-split all weights (1024 blocks cover 512*512 elems)
    split_w<<<1024,256>>>(Wh,  W_WH);
    split_w<<<1024,256>>>(Wz,  W_WZ);
    split_w<<<1024,256>>>(Wr,  W_WR);
    split_w<<<1024,256>>>(Uh,  W_UH);
    split_w<<<1024,256>>>(Uz,  W_UZ);
    split_w<<<1024,256>>>(Ur,  W_UR);
    split_w<<<1024,256>>>(Whd, W_WHD);
    split_w<<<1024,256>>>(Wzd, W_WZD);
    split_w<<<1024,256>>>(Wrd, W_WRD);
    split_w<<<1024,256>>>(Uhd, W_UHD);
    split_w<<<1024,256>>>(Uzd, W_UZD);
    split_w<<<1024,256>>>(Urd, W_URD);
    split_w<<<1024,256>>>(W1,  W_W1);
    split_w<<<1024,256>>>(W2,  W_W2);

    static const int LS[12] = {0,2048,3072,3584,3840,3968,4032,4064,4080,4088,4092,4094};
    static const int LG[12] = {11,10,9,8,7,6,5,4,3,2,1,0};

    auto gemm = [&](int asel, int w0, int w1, int w2,
                    const float* bb0, const float* bb1, const float* bb2,
                    int csel, float* cptr, int ldc, int ccol,
                    int M, int N, int mode, int ptlog, int a_start, int accum)
    {
        dim3 grid(N/64, (M+63)/64);
        mma_gemm<<<grid, 128>>>(feat, asel, w0, w1, w2, bb0, bb1, bb2,
                                cptr, csel, ldc, ccol, M, mode, ptlog, a_start, accum);
    };

    // ---- leaves ----
    {
        int M = NB * 2048;
        gemm(0, W_WZ, W_WH, -1, nullptr, nullptr, nullptr,
             0, nullptr, 1536, 0, M, 1024, 0, 11, 0, 0);
        leaf_epi<<<(M*HDIM + 255)/256, 256>>>(M, 11);
    }

    // ---- bottom-up ----
    for (int l = 0; l < 11; l++) {
        int M   = NB << LG[l+1];
        int lg  = LG[l+1];
        int sst = LS[l], fst = LS[l+1];
        gemm(0, W_WZ, W_WR, W_WH, bUz, bUr, nullptr, 0, nullptr, 1536, 0, M, 1536, 0, lg, fst, 0);
        gemm(1, W_UZ, W_UR, -1,   nullptr, nullptr, nullptr, 0, nullptr, 1536, 0, M, 1024, 1, lg, sst, 1);
        bu_e1<<<(M*HDIM + 255)/256, 256>>>(M, lg, sst);
        gemm(3, W_UH, -1, -1, nullptr, nullptr, nullptr, 0, nullptr, 1536, 1024, M, 512, 3, lg, 0, 1);
        bu_e2<<<(M*HDIM + 255)/256, 256>>>(M, lg, sst, fst);
    }

    root_copy<<<(NB*HDIM + 255)/256, 256>>>();

    // ---- top-down ----
    for (int l = 10; l >= 0; l--) {
        int M   = NB << LG[l];
        int lg  = LG[l];
        int sst = LS[l], fst = LS[l+1];
        gemm(0, W_WZD, W_WRD, W_WHD, bUzd, bUrd, nullptr, 0, nullptr, 1536, 0, M, 1536, 0, lg, sst, 0);
        gemm(2, W_UZD, W_URD, -1,    nullptr, nullptr, nullptr, 0, nullptr, 1536, 0, M, 1024, 2, lg, fst, 1);
        td_e1<<<(M*HDIM + 255)/256, 256>>>(M, lg, fst);
        gemm(3, W_UHD, -1, -1, nullptr, nullptr, nullptr, 0, nullptr, 1536, 1024, M, 512, 3, lg, 0, 1);
        td_e2<<<(M*HDIM + 255)/256, 256>>>(M, lg, fst, sst);
    }

    // ---- output ----
    {
        int M = NTOT;
        gemm(1, W_W1, -1, -1, b1, nullptr, nullptr, 1, out, 512, 0, M, 512, 3, 0, 0, 0);
        gemm(2, W_W2, -1, -1, b2, nullptr, nullptr, 1, out, 512, 0, M, 512, 3, 0, 0, 1);
    }
}

// round 3
// speedup vs baseline: 2.2181x; 1.3443x over previous
#include <cuda_runtime.h>
#include <cuda_bf16.h>
#include <math.h>
#include <stdint.h>

#define HDIM 512
#define NPT  4095
#define NB   8
#define NTOT (NPT*NB)

typedef __nv_bfloat16 bf16;

// ---------------- device scratch ----------------
__device__ float g_h [(size_t)NTOT*HDIM];
__device__ float g_hd[(size_t)NTOT*HDIM];
__device__ float g_z [(size_t)16384*HDIM];
__device__ bf16 g_xs [2][(size_t)NTOT*HDIM];
__device__ bf16 g_hsp[2][(size_t)NTOT*HDIM];
__device__ bf16 g_hdp[2][(size_t)NTOT*HDIM];
__device__ bf16 g_HS [2][(size_t)8192*HDIM];
__device__ bf16 g_V  [2][(size_t)16384*HDIM];
__device__ bf16 g_W  [2][(size_t)7*512*1024];

__device__ __forceinline__ float sigf(float x){ return 1.f/(1.f+expf(-x)); }
__device__ __forceinline__ void split1(float x, bf16& h, bf16& l){
    h = __float2bfloat16(x);
    l = __float2bfloat16(x - __bfloat162float(h));
}

// ---------------- split kernels ----------------
__global__ void split_stack(const float* __restrict__ Wp, const float* __restrict__ Up, int slot)
{
    int idx = blockIdx.x*256 + threadIdx.x;   // 512*1024
    int n = idx >> 10, k = idx & 1023;
    float x = (k < 512) ? Wp[n*512 + k] : Up[n*512 + (k-512)];
    bf16 h,l; split1(x,h,l);
    size_t o = (size_t)slot*512*1024 + idx;
    g_W[0][o]=h; g_W[1][o]=l;
}

__global__ void split_feat(const float* __restrict__ src)
{
    size_t idx = (size_t)blockIdx.x*256 + threadIdx.x;
    float x = src[idx];
    bf16 h,l; split1(x,h,l);
    g_xs[0][idx]=h; g_xs[1][idx]=l;
}

__global__ void hsum_k(int M, int lg, int sst)
{
    int idx = blockIdx.x*256 + threadIdx.x;
    if (idx >= M*HDIM) return;
    int m = idx >> 9, k = idx & 511;
    int tree = m >> lg, pos = m & ((1<<lg)-1);
    int c0 = tree*NPT + sst + (pos<<1);
    float s = g_h[(size_t)c0*HDIM + k] + g_h[(size_t)(c0+1)*HDIM + k];
    bf16 h,l; split1(s,h,l);
    g_HS[0][(size_t)m*HDIM+k]=h; g_HS[1][(size_t)m*HDIM+k]=l;
}

__global__ void root_copy()
{
    int idx = blockIdx.x*256 + threadIdx.x;
    if (idx >= NB*HDIM) return;
    int tree = idx >> 9, k = idx & 511;
    size_t o = (size_t)(tree*NPT + NPT-1)*HDIM + k;
    float v = g_h[o];
    g_hd[o] = v;
    bf16 h,l; split1(v,h,l);
    g_hdp[0][o]=h; g_hdp[1][o]=l;
}

// ---------------- PTX helpers ----------------
#define MMA_BF16(d, a, b) asm volatile( \
  "mma.sync.aligned.m16n8k16.row.col.f32.bf16.bf16.f32 " \
  "{%0,%1,%2,%3}, {%4,%5,%6,%7}, {%8,%9}, {%0,%1,%2,%3};\n" \
  : "+f"(d[0]),"+f"(d[1]),"+f"(d[2]),"+f"(d[3]) \
  : "r"(a[0]),"r"(a[1]),"r"(a[2]),"r"(a[3]), "r"(b[0]),"r"(b[1]))

#define LDSM4(r0,r1,r2,r3,addr) asm volatile( \
  "ldmatrix.sync.aligned.m8n8.x4.shared.b16 {%0,%1,%2,%3}, [%4];\n" \
  : "=r"(r0),"=r"(r1),"=r"(r2),"=r"(r3) : "r"(addr))

#define CPA(dst,src) asm volatile("cp.async.cg.shared.global [%0], [%1], 16;\n"::"r"(dst),"l"(src))
#define CPC()  asm volatile("cp.async.commit_group;\n")
#define CPW1() asm volatile("cp.async.wait_group 1;\n")
#define CPW0() asm volatile("cp.async.wait_group 0;\n")

__device__ __forceinline__ const bf16* act_base(int sel, int part){
    switch(sel){
        case 0:  return g_xs[part];
        case 1:  return g_hsp[part];
        case 2:  return g_hdp[part];
        case 3:  return g_HS[part];
        default: return g_V[part];
    }
}
__device__ __forceinline__ int rowmap(int m, int mode, int start, int lg){
    if (mode == 3) return m;
    int tree = m >> lg, pos = m & ((1<<lg)-1);
    if (mode == 0) return tree*NPT + start + pos;
    return tree*NPT + start + (pos>>1);   // mode 2: father
}

// ---------------- fused split-bf16 tensor-core GEMM ----------------
// out tile: 128 rows x 64 cols x NG gates. K = kend (512 or 1024).
// A seg0 (k<512) and seg1 (k>=512) have independent base/gather.
// epi: 0 leaf, 1 zr_bu, 2 zr_td, 3 th_bu, 4 th_td, 5 out
template<int NG>
__global__ __launch_bounds__(256,1)
void mma_g(int kend,
           int a0sel,int a0mode,int a0start,
           int a1sel,int a1mode,int a1start,
           int slot0,int slot1,
           const float* __restrict__ bias0, const float* __restrict__ bias1,
           int M, int lg, int epi, int e_sst, int e_fst,
           float* __restrict__ outp)
{
    extern __shared__ uint32_t smx[];
    const uint32_t sb = (uint32_t)__cvta_generic_to_shared(smx);
    const int tid = threadIdx.x;
    const int m0 = blockIdx.y << 7;
    const int n0 = blockIdx.x << 6;

    // ---- loader setup: A ----
    const int lrow = tid >> 1;
    const int am = min(m0 + lrow, M-1);
    const bf16* a0h = act_base(a0sel,0) + (size_t)rowmap(am,a0mode,a0start,lg)*HDIM;
    const bf16* a0l = act_base(a0sel,1) + (size_t)rowmap(am,a0mode,a0start,lg)*HDIM;
    const bf16* a1h = a0h; const bf16* a1l = a0l;
    if (kend > 512){
        a1h = act_base(a1sel,0) + (size_t)rowmap(am,a1mode,a1start,lg)*HDIM;
        a1l = act_base(a1sel,1) + (size_t)rowmap(am,a1mode,a1start,lg)*HDIM;
    }
    const int ac0 = (tid & 1) * 2;

    // ---- loader setup: B ----
    const int bg   = tid >> 7;
    const int brem = tid & 127;
    const int brow = brem >> 1;
    const int bc0  = (brem & 1) * 2;
    const int slotg = bg ? slot1 : slot0;
    const bf16* bsh = g_W[0] + (size_t)slotg*512*1024 + (size_t)(n0+brow)*1024;
    const bf16* bsl = g_W[1] + (size_t)slotg*512*1024 + (size_t)(n0+brow)*1024;
    const bool bact = (bg < NG);

    float acc[NG][2][4][4];
    #pragma unroll
    for (int g=0;g<NG;g++)
      #pragma unroll
      for (int a=0;a<2;a++)
        #pragma unroll
        for (int b=0;b<4;b++)
          #pragma unroll
          for (int c=0;c<4;c++) acc[g][a][b][c]=0.f;

    const int niter = kend >> 5;

    auto LOAD = [&](int s, int kt){
        const bf16* ph = (kt < 512) ? a0h : a1h;
        const bf16* pl = (kt < 512) ? a0l : a1l;
        int kl = kt & 511;
        #pragma unroll
        for (int j=0;j<2;j++){
            int c = ac0 + j;
            CPA(sb + (uint32_t)(s*5120 +          lrow*20 + c*4)*4, ph + kl + c*8);
            CPA(sb + (uint32_t)(s*5120 + 2560 +   lrow*20 + c*4)*4, pl + kl + c*8);
        }
        if (bact){
            #pragma unroll
            for (int j=0;j<2;j++){
                int c = bc0 + j;
                CPA(sb + (uint32_t)(10240 + s*5120 + bg*2560 +        brow*20 + c*4)*4, bsh + kt + c*8);
                CPA(sb + (uint32_t)(10240 + s*5120 + bg*2560 + 1280 + brow*20 + c*4)*4, bsl + kt + c*8);
            }
        }
    };

    const int L   = tid & 31;
    const int wid = tid >> 5;
    const int wm  = (wid >> 1) << 5;
    const int wn  = (wid &  1) << 5;

    auto COMP = [&](int s){
        #pragma unroll
        for (int ks=0; ks<2; ks++){
            uint32_t af[2][2][4];
            #pragma unroll
            for (int p=0;p<2;p++)
              #pragma unroll
              for (int mt=0;mt<2;mt++){
                  uint32_t ad = sb + (uint32_t)(s*5120 + p*2560 + (wm + mt*16 + (L&15))*20)*4
                                   + ((L>>4)<<4) + (ks<<5);
                  LDSM4(af[p][mt][0],af[p][mt][1],af[p][mt][2],af[p][mt][3], ad);
              }
            uint32_t bfr[NG][2][4][2];
            #pragma unroll
            for (int g=0;g<NG;g++)
              #pragma unroll
              for (int p=0;p<2;p++)
                #pragma unroll
                for (int tp=0;tp<2;tp++){
                    int n = wn + tp*16 + (L&7) + ((L>>4)<<3);
                    uint32_t bd = sb + (uint32_t)(10240 + s*5120 + g*2560 + p*1280 + n*20)*4
                                     + (((L>>3)&1)<<4) + (ks<<5);
                    uint32_t r0,r1,r2,r3;
                    LDSM4(r0,r1,r2,r3,bd);
                    bfr[g][p][tp*2  ][0]=r0; bfr[g][p][tp*2  ][1]=r1;
                    bfr[g][p][tp*2+1][0]=r2; bfr[g][p][tp*2+1][1]=r3;
                }
            #pragma unroll
            for (int g=0;g<NG;g++)
              #pragma unroll
              for (int mt=0;mt<2;mt++)
                #pragma unroll
                for (int nt=0;nt<4;nt++){
                    MMA_BF16(acc[g][mt][nt], af[0][mt], bfr[g][0][nt]);
                    MMA_BF16(acc[g][mt][nt], af[0][mt], bfr[g][1][nt]);
                    MMA_BF16(acc[g][mt][nt], af[1][mt], bfr[g][0][nt]);
                }
        }
    };

    LOAD(0, 0); CPC();
    for (int it=0; it<niter; ++it){
        if (it+1 < niter){ LOAD((it+1)&1, (it+1)<<5); CPC(); CPW1(); }
        else             { CPW0(); }
        __syncthreads();
        COMP(it & 1);
        __syncthreads();
    }

    // ---------------- fused epilogue ----------------
    #pragma unroll
    for (int mt=0;mt<2;mt++)
    #pragma unroll
    for (int e2=0;e2<2;e2++){
        int r = m0 + wm + mt*16 + (L>>2) + e2*8;
        if (r >= M) continue;
        int tree = r >> lg, pos = r & ((1<<lg)-1);
        #pragma unroll
        for (int nt=0;nt<4;nt++){
            int c = n0 + wn + nt*8 + ((L&3)<<1);
            float v0 = acc[0][mt][nt][e2*2+0];
            float v1 = acc[0][mt][nt][e2*2+1];
            if (epi == 5){
                outp[(size_t)r*HDIM + c]   = v0 + bias0[c]   + bias1[c];
                outp[(size_t)r*HDIM + c+1] = v1 + bias0[c+1] + bias1[c+1];
            } else if (epi == 0){
                float u0 = acc[NG-1][mt][nt][e2*2+0], u1 = acc[NG-1][mt][nt][e2*2+1];
                int node = tree*NPT + e_fst + pos;
                size_t o = (size_t)node*HDIM + c;
                float h0 = (1.f - sigf(v0)) * tanhf(u0);
                float h1 = (1.f - sigf(v1)) * tanhf(u1);
                g_h[o]=h0; g_h[o+1]=h1;
                bf16 hh,ll;
                split1(h0,hh,ll); g_hsp[0][o]=hh;   g_hsp[1][o]=ll;
                split1(h1,hh,ll); g_hsp[0][o+1]=hh; g_hsp[1][o+1]=ll;
            } else if (epi == 1 || epi == 2){
                float u0 = acc[NG-1][mt][nt][e2*2+0], u1 = acc[NG-1][mt][nt][e2*2+1];
                float z0 = sigf(v0 + bias0[c]),  z1 = sigf(v1 + bias0[c+1]);
                float r0 = sigf(u0 + bias1[c]),  r1 = sigf(u1 + bias1[c+1]);
                float hs0, hs1;
                if (epi == 1){
                    int c0n = tree*NPT + e_sst + (pos<<1);
                    size_t oc = (size_t)c0n*HDIM + c;
                    hs0 = g_h[oc]   + g_h[oc+HDIM];
                    hs1 = g_h[oc+1] + g_h[oc+1+HDIM];
                } else {
                    int fn = tree*NPT + e_fst + (pos>>1);
                    size_t of = (size_t)fn*HDIM + c;
                    hs0 = g_hd[of]; hs1 = g_hd[of+1];
                }
                size_t om = (size_t)r*HDIM + c;
                g_z[om]=z0; g_z[om+1]=z1;
                float V0 = r0*hs0, V1 = r1*hs1;
                bf16 hh,ll;
                split1(V0,hh,ll); g_V[0][om]=hh;   g_V[1][om]=ll;
                split1(V1,hh,ll); g_V[0][om+1]=hh; g_V[1][om+1]=ll;
            } else {   // epi 3 / 4
                float cand0 = tanhf(v0), cand1 = tanhf(v1);
                size_t om = (size_t)r*HDIM + c;
                float z0 = g_z[om], z1 = g_z[om+1];
                float hs0, hs1; int node;
                if (epi == 3){
                    int c0n = tree*NPT + e_sst + (pos<<1);
                    size_t oc = (size_t)c0n*HDIM + c;
                    hs0 = g_h[oc]   + g_h[oc+HDIM];
                    hs1 = g_h[oc+1] + g_h[oc+1+HDIM];
                    node = tree*NPT + e_fst + pos;
                } else {
                    int fn = tree*NPT + e_fst + (pos>>1);
                    size_t of = (size_t)fn*HDIM + c;
                    hs0 = g_hd[of]; hs1 = g_hd[of+1];
                    node = tree*NPT + e_sst + pos;
                }
                float h0 = z0*hs0 + (1.f-z0)*cand0;
                float h1 = z1*hs1 + (1.f-z1)*cand1;
                size_t o = (size_t)node*HDIM + c;
                bf16 hh,ll;
                if (epi == 3){
                    g_h[o]=h0; g_h[o+1]=h1;
                    split1(h0,hh,ll); g_hsp[0][o]=hh;   g_hsp[1][o]=ll;
                    split1(h1,hh,ll); g_hsp[0][o+1]=hh; g_hsp[1][o+1]=ll;
                } else {
                    g_hd[o]=h0; g_hd[o+1]=h1;
                    split1(h0,hh,ll); g_hdp[0][o]=hh;   g_hdp[1][o]=ll;
                    split1(h1,hh,ll); g_hdp[0][o+1]=hh; g_hdp[1][o+1]=ll;
                }
            }
        }
    }
}

// ---------------- host orchestration ----------------
extern "C" void kernel_launch(void* const* d_in, const int* in_sizes, int n_in,
                              void* d_out, int out_size)
{
    (void)in_sizes; (void)n_in; (void)out_size;
    const float* feat = (const float*)d_in[0];
    const float* Wh   = (const float*)d_in[1];
    const float* Wz   = (const float*)d_in[2];
    const float* Wr   = (const float*)d_in[3];
    const float* Uh   = (const float*)d_in[4];
    const float* Uz   = (const float*)d_in[5];
    const float* bUz  = (const float*)d_in[6];
    const float* Ur   = (const float*)d_in[7];
    const float* bUr  = (const float*)d_in[8];
    const float* Whd  = (const float*)d_in[9];
    const float* Wzd  = (const float*)d_in[10];
    const float* Wrd  = (const float*)d_in[11];
    const float* Uhd  = (const float*)d_in[12];
    const float* Uzd  = (const float*)d_in[13];
    const float* bUzd = (const float*)d_in[14];
    const float* Urd  = (const float*)d_in[15];
    const float* bUrd = (const float*)d_in[16];
    const float* W1   = (const float*)d_in[17];
    const float* b1   = (const float*)d_in[18];
    const float* W2   = (const float*)d_in[19];
    const float* b2   = (const float*)d_in[20];
    float* out = (float*)d_out;

    const int SMEM = 81920;
    cudaFuncSetAttribute((const void*)mma_g<1>, cudaFuncAttributeMaxDynamicSharedMemorySize, SMEM);
    cudaFuncSetAttribute((const void*)mma_g<2>, cudaFuncAttributeMaxDynamicSharedMemorySize, SMEM);

    // stacked weight slots: 0 z(Wz,Uz) 1 r(Wr,Ur) 2 h(Wh,Uh) 3 zd 4 rd 5 hd 6 out(W1,W2)
    split_stack<<<2048,256>>>(Wz,  Uz,  0);
    split_stack<<<2048,256>>>(Wr,  Ur,  1);
    split_stack<<<2048,256>>>(Wh,  Uh,  2);
    split_stack<<<2048,256>>>(Wzd, Uzd, 3);
    split_stack<<<2048,256>>>(Wrd, Urd, 4);
    split_stack<<<2048,256>>>(Whd, Uhd, 5);
    split_stack<<<2048,256>>>(W1,  W2,  6);
    split_feat<<<65520,256>>>(feat);

    static const int LS[12] = {0,2048,3072,3584,3840,3968,4032,4064,4080,4088,4092,4094};
    static const int LG[12] = {11,10,9,8,7,6,5,4,3,2,1,0};

    // ---- leaves: z=sig(X@Wz), th=X@Wh -> h ----
    {
        int M = NB*2048;
        dim3 g(8, (M+127)/128);
        mma_g<2><<<g,256,SMEM>>>(512, 0,0,0,  0,0,0, 0,2,
                                 nullptr,nullptr, M, 11, 0, 0, 0, nullptr);
    }

    // ---- bottom-up ----
    for (int l=0; l<11; l++){
        int lgf = LG[l+1];
        int M   = NB << lgf;
        int sst = LS[l], fst = LS[l+1];
        hsum_k<<<(M*HDIM+255)/256,256>>>(M, lgf, sst);
        dim3 g(8,(M+127)/128);
        // z,r: [X|HS] @ [Wz;Uz],[Wr;Ur]
        mma_g<2><<<g,256,SMEM>>>(1024, 0,0,fst, 3,3,0, 0,1,
                                 bUz,bUr, M, lgf, 1, sst, fst, nullptr);
        // th: [X|V] @ [Wh;Uh] -> h
        mma_g<1><<<g,256,SMEM>>>(1024, 0,0,fst, 4,3,0, 2,0,
                                 nullptr,nullptr, M, lgf, 3, sst, fst, nullptr);
    }

    root_copy<<<16,256>>>();

    // ---- top-down ----
    for (int l=10; l>=0; l--){
        int lgs = LG[l];
        int M   = NB << lgs;
        int sst = LS[l], fst = LS[l+1];
        dim3 g(8,(M+127)/128);
        // zd,rd: [X|HF] @ [Wzd;Uzd],[Wrd;Urd]
        mma_g<2><<<g,256,SMEM>>>(1024, 0,0,sst, 2,2,fst, 3,4,
                                 bUzd,bUrd, M, lgs, 2, sst, fst, nullptr);
        // th: [X|V] @ [Whd;Uhd] -> hd
        mma_g<1><<<g,256,SMEM>>>(1024, 0,0,sst, 4,3,0, 5,0,
                                 nullptr,nullptr, M, lgs, 4, sst, fst, nullptr);
    }

    // ---- output: [h|hd] @ [W1;W2] + b1 + b2 ----
    {
        int M = NTOT;
        dim3 g(8,(M+127)/128);
        mma_g<1><<<g,256,SMEM>>>(1024, 1,3,0, 2,3,0, 6,0,
                                 b1,b2, M, 1, 5, 0, 0, out);
    }
}

// round 5
// speedup vs baseline: 2.8567x; 1.2879x over previous
#include <cuda_runtime.h>
#include <cuda_fp16.h>
#include <math.h>
#include <stdint.h>

#define HDIM 512
#define NPT  4095
#define NB   8
#define NTOT (NPT*NB)

typedef __half hlf;

// ---------------- device scratch ----------------
__device__ float g_h [(size_t)NTOT*HDIM];
__device__ float g_hd[(size_t)NTOT*HDIM];
__device__ float g_z [(size_t)16384*HDIM];
__device__ hlf g_xs [2][(size_t)NTOT*HDIM];     // feat split hi/lo
__device__ hlf g_hsp[2][(size_t)NTOT*HDIM];     // h split
__device__ hlf g_hdp[2][(size_t)NTOT*HDIM];     // hd split
__device__ hlf g_V  [2][(size_t)16384*HDIM];    // r*h split
__device__ hlf g_W  [(size_t)7*512*1024];       // stacked weights, fp16

__device__ __forceinline__ float sigf(float x){ return 1.f/(1.f+expf(-x)); }
__device__ __forceinline__ void split1(float x, hlf& h, hlf& l){
    h = __float2half_rn(x);
    l = __float2half_rn(x - __half2float(h));
}
__device__ __forceinline__ uint32_t pack2(hlf a, hlf b){
    __half2 p = __halves2half2(a,b);
    return *reinterpret_cast<uint32_t*>(&p);
}
__device__ __forceinline__ void st_split2(hlf* hi, hlf* lo, float x0, float x1){
    hlf h0,l0,h1,l1; split1(x0,h0,l0); split1(x1,h1,l1);
    *reinterpret_cast<__half2*>(hi) = __halves2half2(h0,h1);
    *reinterpret_cast<__half2*>(lo) = __halves2half2(l0,l1);
}

// ---------------- setup kernels ----------------
__global__ void split_w(const float* Wz,const float* Uz,const float* Wr,const float* Ur,
                        const float* Wh,const float* Uh,const float* Wzd,const float* Uzd,
                        const float* Wrd,const float* Urd,const float* Whd,const float* Uhd,
                        const float* W1,const float* W2)
{
    int slot = blockIdx.y;
    const float* Wp; const float* Up;
    switch(slot){
        case 0: Wp=Wz;  Up=Uz;  break;
        case 1: Wp=Wr;  Up=Ur;  break;
        case 2: Wp=Wh;  Up=Uh;  break;
        case 3: Wp=Wzd; Up=Uzd; break;
        case 4: Wp=Wrd; Up=Urd; break;
        case 5: Wp=Whd; Up=Uhd; break;
        default:Wp=W1;  Up=W2;  break;
    }
    int idx = blockIdx.x*256 + threadIdx.x;   // 512*1024
    int n = idx >> 10, k = idx & 1023;
    float x = (k < 512) ? Wp[n*512 + k] : Up[n*512 + (k-512)];
    g_W[(size_t)slot*524288 + idx] = __float2half_rn(x);
}

__global__ void split_feat(const float* __restrict__ src)
{
    size_t idx = (size_t)blockIdx.x*256 + threadIdx.x;
    float x = src[idx];
    hlf h,l; split1(x,h,l);
    g_xs[0][idx]=h; g_xs[1][idx]=l;
}

__global__ void root_copy()
{
    int idx = blockIdx.x*256 + threadIdx.x;
    if (idx >= NB*HDIM) return;
    int tree = idx >> 9, k = idx & 511;
    size_t o = (size_t)(tree*NPT + NPT-1)*HDIM + k;
    float v = g_h[o];
    g_hd[o] = v;
    hlf h,l; split1(v,h,l);
    g_hdp[0][o]=h; g_hdp[1][o]=l;
}

// ---------------- PTX helpers ----------------
#define MMA_F16(d, a, b) asm volatile( \
  "mma.sync.aligned.m16n8k16.row.col.f32.f16.f16.f32 " \
  "{%0,%1,%2,%3}, {%4,%5,%6,%7}, {%8,%9}, {%0,%1,%2,%3};\n" \
  : "+f"(d[0]),"+f"(d[1]),"+f"(d[2]),"+f"(d[3]) \
  : "r"(a[0]),"r"(a[1]),"r"(a[2]),"r"(a[3]), "r"(b[0]),"r"(b[1]))

#define LDSM4(r0,r1,r2,r3,addr) asm volatile( \
  "ldmatrix.sync.aligned.m8n8.x4.shared.b16 {%0,%1,%2,%3}, [%4];\n" \
  : "=r"(r0),"=r"(r1),"=r"(r2),"=r"(r3) : "r"(addr))

#define CPA(dst,src) asm volatile("cp.async.cg.shared.global [%0], [%1], 16;\n"::"r"(dst),"l"(src))
#define CPC()  asm volatile("cp.async.commit_group;\n")
#define CPW1() asm volatile("cp.async.wait_group 1;\n")
#define CPW0() asm volatile("cp.async.wait_group 0;\n")

__device__ __forceinline__ const hlf* act_base(int sel, int part){
    switch(sel){
        case 0:  return g_xs[part];
        case 1:  return g_hsp[part];
        case 2:  return g_hdp[part];
        default: return g_V[part];
    }
}
__device__ __forceinline__ int rowmap(int m, int mode, int start, int lg){
    if (mode == 3) return m;
    int tree = m >> lg, pos = m & ((1<<lg)-1);
    if (mode == 0) return tree*NPT + start + pos;
    return tree*NPT + start + (pos>>1);   // mode 2: father
}

// ---------------- fused fp16 2-pass tensor-core GEMM ----------------
// Tile 128 rows x 64 cols x NG gates, BK=32, double-buffered cp.async.
// A = hi+lo fp16 (split), B = fp16. acc += A_hi@B + A_lo@B.
// Seg0 (k<512) / seg1 (k>=512) have independent gathers; a1mode==1 means
// seg1 = pair-sum of children read from fp32 g_h (computed in-loader).
// epi: 0 leaf, 1 zr_bu, 2 zr_td, 3 th_bu, 4 th_td, 5 out
template<int NG>
__global__ __launch_bounds__(256,1)
void mma_g(int kend,
           int a0sel,int a0mode,int a0start,
           int a1sel,int a1mode,int a1start,
           int slot0,int slot1,
           const float* __restrict__ bias0, const float* __restrict__ bias1,
           int M, int lg, int epi, int e_sst, int e_fst,
           float* __restrict__ outp)
{
    extern __shared__ uint32_t smx[];
    uint32_t sb;
    asm("{ .reg .u64 t; cvta.to.shared.u64 t, %1; cvt.u32.u64 %0, t; }" : "=r"(sb) : "l"(smx));
    const int tid = threadIdx.x;
    const int m0 = blockIdx.y << 7;
    const int n0 = blockIdx.x << 6;

    // ---- A loader setup ----
    const int lrow = tid >> 1;          // 0..127
    const int ac0 = (tid & 1) * 2;      // chunk base (each chunk = 8 halves)
    const int am = min(m0 + lrow, M-1);
    const hlf* a0h = act_base(a0sel,0) + (size_t)rowmap(am,a0mode,a0start,lg)*HDIM;
    const hlf* a0l = act_base(a0sel,1) + (size_t)rowmap(am,a0mode,a0start,lg)*HDIM;
    const hlf* a1h = a0h; const hlf* a1l = a0l;
    const float* ch0 = nullptr; const float* ch1 = nullptr;
    if (kend > 512){
        if (a1mode == 1){
            int tree = am >> lg, pos = am & ((1<<lg)-1);
            int c0n = tree*NPT + a1start + (pos<<1);
            ch0 = g_h + (size_t)c0n*HDIM;
            ch1 = ch0 + HDIM;
        } else {
            a1h = act_base(a1sel,0) + (size_t)rowmap(am,a1mode,a1start,lg)*HDIM;
            a1l = act_base(a1sel,1) + (size_t)rowmap(am,a1mode,a1start,lg)*HDIM;
        }
    }
    // ---- B loader setup ----
    const int bg   = tid >> 7;          // gate
    const int brem = tid & 127;
    const int brow = brem >> 1;
    const int bc0  = (brem & 1) * 2;
    const int slotg = bg ? slot1 : slot0;
    const hlf* bptr = g_W + (size_t)slotg*524288 + (size_t)(n0+brow)*1024;
    const bool bact = (bg < NG);

    float acc[NG][2][4][4];
    #pragma unroll
    for (int g=0;g<NG;g++)
      #pragma unroll
      for (int a=0;a<2;a++)
        #pragma unroll
        for (int b=0;b<4;b++)
          #pragma unroll
          for (int c=0;c<4;c++) acc[g][a][b][c]=0.f;

    auto LOAD = [&](int s, int kt){
        if (kt < 512 || ch0 == nullptr){
            const hlf* ph = (kt<512)? a0h : a1h;
            const hlf* pl = (kt<512)? a0l : a1l;
            int kl = kt & 511;
            #pragma unroll
            for (int j=0;j<2;j++){
                int c = ac0+j;
                CPA(sb + (uint32_t)(s*5120 +        lrow*20 + c*4)*4, ph + kl + c*8);
                CPA(sb + (uint32_t)(s*5120 + 2560 + lrow*20 + c*4)*4, pl + kl + c*8);
            }
        } else {
            int kl = kt - 512;
            #pragma unroll
            for (int j=0;j<2;j++){
                int k = kl + (ac0+j)*8;
                float4 x0 = *(const float4*)(ch0+k);
                float4 x1 = *(const float4*)(ch0+k+4);
                float4 y0 = *(const float4*)(ch1+k);
                float4 y1 = *(const float4*)(ch1+k+4);
                float s0=x0.x+y0.x, s1=x0.y+y0.y, s2=x0.z+y0.z, s3=x0.w+y0.w;
                float s4=x1.x+y1.x, s5=x1.y+y1.y, s6=x1.z+y1.z, s7=x1.w+y1.w;
                hlf h0,l0,h1,l1,h2,l2,h3,l3,h4,l4,h5,l5,h6,l6,h7,l7;
                split1(s0,h0,l0); split1(s1,h1,l1); split1(s2,h2,l2); split1(s3,h3,l3);
                split1(s4,h4,l4); split1(s5,h5,l5); split1(s6,h6,l6); split1(s7,h7,l7);
                int idx = s*5120 + lrow*20 + (ac0+j)*4;
                smx[idx+0]=pack2(h0,h1); smx[idx+1]=pack2(h2,h3);
                smx[idx+2]=pack2(h4,h5); smx[idx+3]=pack2(h6,h7);
                smx[idx+2560+0]=pack2(l0,l1); smx[idx+2560+1]=pack2(l2,l3);
                smx[idx+2560+2]=pack2(l4,l5); smx[idx+2560+3]=pack2(l6,l7);
            }
        }
        if (bact){
            #pragma unroll
            for (int j=0;j<2;j++){
                int c = bc0+j;
                CPA(sb + (uint32_t)(10240 + s*(NG*1280) + bg*1280 + brow*20 + c*4)*4,
                    bptr + kt + c*8);
            }
        }
    };

    const int L   = tid & 31;
    const int wid = tid >> 5;
    const int wm  = (wid >> 1) << 5;
    const int wn  = (wid &  1) << 5;

    auto COMP = [&](int s){
        #pragma unroll
        for (int ks=0; ks<2; ks++){
            uint32_t af[2][2][4];
            #pragma unroll
            for (int p=0;p<2;p++)
              #pragma unroll
              for (int mt=0;mt<2;mt++){
                  uint32_t ad = sb + (uint32_t)(s*5120 + p*2560 + (wm + mt*16 + (L&15))*20)*4
                                   + ((L>>4)<<4) + (ks<<5);
                  LDSM4(af[p][mt][0],af[p][mt][1],af[p][mt][2],af[p][mt][3], ad);
              }
            uint32_t bfr[NG][4][2];
            #pragma unroll
            for (int g=0;g<NG;g++)
              #pragma unroll
              for (int tp=0;tp<2;tp++){
                  int n = wn + tp*16 + (L&7) + ((L>>4)<<3);
                  uint32_t bd = sb + (uint32_t)(10240 + s*(NG*1280) + g*1280 + n*20)*4
                                   + (((L>>3)&1)<<4) + (ks<<5);
                  uint32_t r0,r1,r2,r3;
                  LDSM4(r0,r1,r2,r3,bd);
                  bfr[g][tp*2  ][0]=r0; bfr[g][tp*2  ][1]=r1;
                  bfr[g][tp*2+1][0]=r2; bfr[g][tp*2+1][1]=r3;
              }
            #pragma unroll
            for (int g=0;g<NG;g++)
              #pragma unroll
              for (int mt=0;mt<2;mt++)
                #pragma unroll
                for (int nt=0;nt<4;nt++){
                    MMA_F16(acc[g][mt][nt], af[0][mt], bfr[g][nt]);
                    MMA_F16(acc[g][mt][nt], af[1][mt], bfr[g][nt]);
                }
        }
    };

    const int niter = kend >> 5;
    LOAD(0,0); CPC();
    for (int it=0; it<niter; ++it){
        if (it+1 < niter){ LOAD((it+1)&1, (it+1)<<5); CPC(); CPW1(); }
        else             { CPW0(); }
        __syncthreads();
        COMP(it & 1);
        __syncthreads();
    }

    // ---------------- fused epilogue ----------------
    #pragma unroll
    for (int mt=0;mt<2;mt++)
    #pragma unroll
    for (int e2=0;e2<2;e2++){
        int r = m0 + wm + mt*16 + (L>>2) + e2*8;
        if (r >= M) continue;
        int tree = r >> lg, pos = r & ((1<<lg)-1);
        #pragma unroll
        for (int nt=0;nt<4;nt++){
            int c = n0 + wn + nt*8 + ((L&3)<<1);
            float v0 = acc[0][mt][nt][e2*2+0];
            float v1 = acc[0][mt][nt][e2*2+1];
            if (epi == 5){
                outp[(size_t)r*HDIM + c]   = v0 + bias0[c]   + bias1[c];
                outp[(size_t)r*HDIM + c+1] = v1 + bias0[c+1] + bias1[c+1];
            } else if (epi == 0){
                float u0 = acc[NG-1][mt][nt][e2*2+0], u1 = acc[NG-1][mt][nt][e2*2+1];
                size_t o = (size_t)(tree*NPT + e_fst + pos)*HDIM + c;
                float h0 = (1.f - sigf(v0)) * tanhf(u0);
                float h1 = (1.f - sigf(v1)) * tanhf(u1);
                g_h[o]=h0; g_h[o+1]=h1;
                st_split2(&g_hsp[0][o], &g_hsp[1][o], h0, h1);
            } else if (epi == 1 || epi == 2){
                float u0 = acc[NG-1][mt][nt][e2*2+0], u1 = acc[NG-1][mt][nt][e2*2+1];
                float z0 = sigf(v0 + bias0[c]),  z1 = sigf(v1 + bias0[c+1]);
                float r0 = sigf(u0 + bias1[c]),  r1 = sigf(u1 + bias1[c+1]);
                float hs0, hs1;
                if (epi == 1){
                    size_t oc = (size_t)(tree*NPT + e_sst + (pos<<1))*HDIM + c;
                    hs0 = g_h[oc]   + g_h[oc+HDIM];
                    hs1 = g_h[oc+1] + g_h[oc+1+HDIM];
                } else {
                    size_t of = (size_t)(tree*NPT + e_fst + (pos>>1))*HDIM + c;
                    hs0 = g_hd[of]; hs1 = g_hd[of+1];
                }
                size_t om = (size_t)r*HDIM + c;
                g_z[om]=z0; g_z[om+1]=z1;
                st_split2(&g_V[0][om], &g_V[1][om], r0*hs0, r1*hs1);
            } else {   // epi 3 / 4
                float cand0 = tanhf(v0), cand1 = tanhf(v1);
                size_t om = (size_t)r*HDIM + c;
                float z0 = g_z[om], z1 = g_z[om+1];
                float hs0, hs1; int node;
                if (epi == 3){
                    size_t oc = (size_t)(tree*NPT + e_sst + (pos<<1))*HDIM + c;
                    hs0 = g_h[oc]   + g_h[oc+HDIM];
                    hs1 = g_h[oc+1] + g_h[oc+1+HDIM];
                    node = tree*NPT + e_fst + pos;
                } else {
                    size_t of = (size_t)(tree*NPT + e_fst + (pos>>1))*HDIM + c;
                    hs0 = g_hd[of]; hs1 = g_hd[of+1];
                    node = tree*NPT + e_sst + pos;
                }
                float h0 = z0*hs0 + (1.f-z0)*cand0;
                float h1 = z1*hs1 + (1.f-z1)*cand1;
                size_t o = (size_t)node*HDIM + c;
                if (epi == 3){
                    g_h[o]=h0; g_h[o+1]=h1;
                    st_split2(&g_hsp[0][o], &g_hsp[1][o], h0, h1);
                } else {
                    g_hd[o]=h0; g_hd[o+1]=h1;
                    st_split2(&g_hdp[0][o], &g_hdp[1][o], h0, h1);
                }
            }
        }
    }
}

// ---------------- host orchestration ----------------
extern "C" void kernel_launch(void* const* d_in, const int* in_sizes, int n_in,
                              void* d_out, int out_size)
{
    (void)in_sizes; (void)n_in; (void)out_size;
    const float* feat = (const float*)d_in[0];
    const float* Wh   = (const float*)d_in[1];
    const float* Wz   = (const float*)d_in[2];
    const float* Wr   = (const float*)d_in[3];
    const float* Uh   = (const float*)d_in[4];
    const float* Uz   = (const float*)d_in[5];
    const float* bUz  = (const float*)d_in[6];
    const float* Ur   = (const float*)d_in[7];
    const float* bUr  = (const float*)d_in[8];
    const float* Whd  = (const float*)d_in[9];
    const float* Wzd  = (const float*)d_in[10];
    const float* Wrd  = (const float*)d_in[11];
    const float* Uhd  = (const float*)d_in[12];
    const float* Uzd  = (const float*)d_in[13];
    const float* bUzd = (const float*)d_in[14];
    const float* Urd  = (const float*)d_in[15];
    const float* bUrd = (const float*)d_in[16];
    const float* W1   = (const float*)d_in[17];
    const float* b1   = (const float*)d_in[18];
    const float* W2   = (const float*)d_in[19];
    const float* b2   = (const float*)d_in[20];
    float* out = (float*)d_out;

    const int SMEM = 61440;
    cudaFuncSetAttribute(mma_g<1>, cudaFuncAttributeMaxDynamicSharedMemorySize, SMEM);
    cudaFuncSetAttribute(mma_g<2>, cudaFuncAttributeMaxDynamicSharedMemorySize, SMEM);

    // slots: 0 [Wz|Uz]  1 [Wr|Ur]  2 [Wh|Uh]  3 [Wzd|Uzd]  4 [Wrd|Urd]  5 [Whd|Uhd]  6 [W1|W2]
    split_w<<<dim3(2048,7),256>>>(Wz,Uz, Wr,Ur, Wh,Uh, Wzd,Uzd, Wrd,Urd, Whd,Uhd, W1,W2);
    split_feat<<<65520,256>>>(feat);

    static const int LS[12] = {0,2048,3072,3584,3840,3968,4032,4064,4080,4088,4092,4094};
    static const int LG[12] = {11,10,9,8,7,6,5,4,3,2,1,0};

    // ---- leaves: z = sig(X@Wz), th = X@Wh -> h ----
    mma_g<2><<<dim3(8,128),256,SMEM>>>(512, 0,0,0, 0,0,0, 0,2,
                                       nullptr,nullptr, NB*2048, 11, 0, 0, 0, nullptr);

    // ---- bottom-up ----
    for (int l=0; l<11; l++){
        int lgf = LG[l+1];
        int M   = NB << lgf;
        int sst = LS[l], fst = LS[l+1];
        int mb  = (M+127)/128;
        // z,r: [X_fa | sum(children h)] @ [Wz;Uz],[Wr;Ur]
        mma_g<2><<<dim3(8,mb),256,SMEM>>>(1024, 0,0,fst, 0,1,sst, 0,1,
                                          bUz,bUr, M, lgf, 1, sst, fst, nullptr);
        // th: [X_fa | V] @ [Wh;Uh] -> h
        mma_g<1><<<dim3(8,mb),256,SMEM>>>(1024, 0,0,fst, 3,3,0, 2,2,
                                          nullptr,nullptr, M, lgf, 3, sst, fst, nullptr);
    }

    root_copy<<<16,256>>>();

    // ---- top-down ----
    for (int l=10; l>=0; l--){
        int lgs = LG[l];
        int M   = NB << lgs;
        int sst = LS[l], fst = LS[l+1];
        int mb  = (M+127)/128;
        // zd,rd: [X_son | hd_father] @ [Wzd;Uzd],[Wrd;Urd]
        mma_g<2><<<dim3(8,mb),256,SMEM>>>(1024, 0,0,sst, 2,2,fst, 3,4,
                                          bUzd,bUrd, M, lgs, 2, sst, fst, nullptr);
        // th: [X_son | V] @ [Whd;Uhd] -> hd
        mma_g<1><<<dim3(8,mb),256,SMEM>>>(1024, 0,0,sst, 3,3,0, 5,5,
                                          nullptr,nullptr, M, lgs, 4, sst, fst, nullptr);
    }

    // ---- output: [h|hd] @ [W1;W2] + b1 + b2 ----
    mma_g<1><<<dim3(8,256),256,SMEM>>>(1024, 1,3,0, 2,3,0, 6,6,
                                       b1,b2, NTOT, 1, 5, 0, 0, out);
}

// round 6
// speedup vs baseline: 3.1690x; 1.1093x over previous
#include <cuda_runtime.h>
#include <cuda_fp16.h>
#include <math.h>
#include <stdint.h>

#define HDIM 512
#define NPT  4095
#define NB   8
#define NTOT (NPT*NB)

typedef __half hlf;

// ---------------- device scratch ----------------
__device__ float g_h [(size_t)NTOT*HDIM];
__device__ float g_hd[(size_t)NTOT*HDIM];
__device__ float g_z [(size_t)16384*HDIM];
__device__ hlf g_xs [2][(size_t)NTOT*HDIM];
__device__ hlf g_hsp[2][(size_t)NTOT*HDIM];
__device__ hlf g_hdp[2][(size_t)NTOT*HDIM];
__device__ hlf g_V  [2][(size_t)16384*HDIM];
__device__ hlf g_W  [(size_t)7*512*1024];

__device__ __forceinline__ float sigf(float x){ return 1.f/(1.f+expf(-x)); }
__device__ __forceinline__ void split1(float x, hlf& h, hlf& l){
    h = __float2half_rn(x);
    l = __float2half_rn(x - __half2float(h));
}
__device__ __forceinline__ uint32_t pack2(hlf a, hlf b){
    __half2 p = __halves2half2(a,b);
    return *reinterpret_cast<uint32_t*>(&p);
}
__device__ __forceinline__ void st_split2(hlf* hi, hlf* lo, float x0, float x1){
    hlf h0,l0,h1,l1; split1(x0,h0,l0); split1(x1,h1,l1);
    *reinterpret_cast<__half2*>(hi) = __halves2half2(h0,h1);
    *reinterpret_cast<__half2*>(lo) = __halves2half2(l0,l1);
}
__device__ __forceinline__ void st_split4(hlf* hi, hlf* lo, float a,float b,float c,float d){
    hlf h0,l0,h1,l1,h2,l2,h3,l3;
    split1(a,h0,l0); split1(b,h1,l1); split1(c,h2,l2); split1(d,h3,l3);
    uint2 vh; vh.x = pack2(h0,h1); vh.y = pack2(h2,h3);
    uint2 vl; vl.x = pack2(l0,l1); vl.y = pack2(l2,l3);
    *reinterpret_cast<uint2*>(hi) = vh;
    *reinterpret_cast<uint2*>(lo) = vl;
}

// ---------------- setup kernels ----------------
__global__ void split_w(const float* Wz,const float* Uz,const float* Wr,const float* Ur,
                        const float* Wh,const float* Uh,const float* Wzd,const float* Uzd,
                        const float* Wrd,const float* Urd,const float* Whd,const float* Uhd,
                        const float* W1,const float* W2)
{
    int slot = blockIdx.y;
    const float* Wp; const float* Up;
    switch(slot){
        case 0: Wp=Wz;  Up=Uz;  break;
        case 1: Wp=Wr;  Up=Ur;  break;
        case 2: Wp=Wh;  Up=Uh;  break;
        case 3: Wp=Wzd; Up=Uzd; break;
        case 4: Wp=Wrd; Up=Urd; break;
        case 5: Wp=Whd; Up=Uhd; break;
        default:Wp=W1;  Up=W2;  break;
    }
    int idx = blockIdx.x*256 + threadIdx.x;
    int n = idx >> 10, k = idx & 1023;
    float x = (k < 512) ? Wp[n*512 + k] : Up[n*512 + (k-512)];
    g_W[(size_t)slot*524288 + idx] = __float2half_rn(x);
}

__global__ void split_feat(const float* __restrict__ src)
{
    size_t idx = (size_t)blockIdx.x*256 + threadIdx.x;
    float x = src[idx];
    hlf h,l; split1(x,h,l);
    g_xs[0][idx]=h; g_xs[1][idx]=l;
}

__global__ void root_copy()
{
    int idx = blockIdx.x*256 + threadIdx.x;
    if (idx >= NB*HDIM) return;
    int tree = idx >> 9, k = idx & 511;
    size_t o = (size_t)(tree*NPT + NPT-1)*HDIM + k;
    float v = g_h[o];
    g_hd[o] = v;
    hlf h,l; split1(v,h,l);
    g_hdp[0][o]=h; g_hdp[1][o]=l;
}

// ---------------- PTX helpers ----------------
#define MMA_F16(d, a, b) asm volatile( \
  "mma.sync.aligned.m16n8k16.row.col.f32.f16.f16.f32 " \
  "{%0,%1,%2,%3}, {%4,%5,%6,%7}, {%8,%9}, {%0,%1,%2,%3};\n" \
  : "+f"(d[0]),"+f"(d[1]),"+f"(d[2]),"+f"(d[3]) \
  : "r"(a[0]),"r"(a[1]),"r"(a[2]),"r"(a[3]), "r"(b[0]),"r"(b[1]))

#define LDSM4(r0,r1,r2,r3,addr) asm volatile( \
  "ldmatrix.sync.aligned.m8n8.x4.shared.b16 {%0,%1,%2,%3}, [%4];\n" \
  : "=r"(r0),"=r"(r1),"=r"(r2),"=r"(r3) : "r"(addr))

#define CPA(dst,src) asm volatile("cp.async.cg.shared.global [%0], [%1], 16;\n"::"r"(dst),"l"(src))
#define CPC()  asm volatile("cp.async.commit_group;\n")
#define CPW1() asm volatile("cp.async.wait_group 1;\n")
#define CPW0() asm volatile("cp.async.wait_group 0;\n")

__device__ __forceinline__ const hlf* act_base(int sel, int part){
    switch(sel){
        case 0:  return g_xs[part];
        case 1:  return g_hsp[part];
        case 2:  return g_hdp[part];
        default: return g_V[part];
    }
}
__device__ __forceinline__ int rowmap(int m, int mode, int start, int lg){
    if (mode == 3) return m;
    int tree = m >> lg, pos = m & ((1<<lg)-1);
    if (mode == 0) return tree*NPT + start + pos;
    return tree*NPT + start + (pos>>1);   // mode 2: father
}

// smem layout (words): A stage = hi[128][36] + lo[128][36] = 9216
//   A: s*9216 (+4608 for lo)     B: 18432 + s*4608   total 27648 w = 110592 B
#define AW    36
#define A_ST  9216
#define B_OFF 18432
#define B_ST  4608
#define SMEMB 110592
#define SP    132     // epilogue exchange row stride (words)

// ---------------- fused fp16 2-pass tensor-core GEMM ----------------
// CTA tile: 128 rows x 128 logical cols (NG=2: 64 cols x {gate0,gate1}; NG=1: 128 cols)
// 512 threads, 4x4 warp grid, 32x32 warp tiles, BK=64, double-buffered cp.async.
// epi: 0 leaf, 1 zr_bu, 2 zr_td, 3 th_bu, 4 th_td, 5 out
template<int NG>
__global__ __launch_bounds__(512,1)
void mma_g(int kend,
           int a0sel,int a0mode,int a0start,
           int a1sel,int a1mode,int a1start,
           int slot0,int slot1,
           const float* __restrict__ bias0, const float* __restrict__ bias1,
           int M, int lg, int epi, int e_sst, int e_fst,
           float* __restrict__ outp)
{
    extern __shared__ uint32_t smx[];
    uint32_t sb;
    asm("{ .reg .u64 t; cvta.to.shared.u64 t, %1; cvt.u32.u64 %0, t; }" : "=r"(sb) : "l"(smx));
    const int tid = threadIdx.x;
    const int m0 = blockIdx.y << 7;
    const int n0 = blockIdx.x * (NG==2 ? 64 : 128);

    // ---- loader setup (shared row/chunk decomposition) ----
    const int row = tid >> 2;          // 0..127
    const int cb  = (tid & 3) * 2;     // first of 2 16B chunks (8 halves each)

    const int am = min(m0 + row, M-1);
    const hlf* a0h = act_base(a0sel,0) + (size_t)rowmap(am,a0mode,a0start,lg)*HDIM;
    const hlf* a0l = act_base(a0sel,1) + (size_t)rowmap(am,a0mode,a0start,lg)*HDIM;
    const hlf* a1h = a0h; const hlf* a1l = a0l;
    const float* ch0 = nullptr; const float* ch1 = nullptr;
    if (kend > 512){
        if (a1mode == 1){
            int tree = am >> lg, pos = am & ((1<<lg)-1);
            int c0n = tree*NPT + a1start + (pos<<1);
            ch0 = g_h + (size_t)c0n*HDIM;
            ch1 = ch0 + HDIM;
        } else {
            a1h = act_base(a1sel,0) + (size_t)rowmap(am,a1mode,a1start,lg)*HDIM;
            a1l = act_base(a1sel,1) + (size_t)rowmap(am,a1mode,a1start,lg)*HDIM;
        }
    }
    // B: smem row r <-> weight col
    int bslot, bcol;
    if (NG==2){ bslot = (row>=64)?slot1:slot0; bcol = n0 + (row&63); }
    else      { bslot = slot0;                 bcol = n0 + row; }
    const hlf* bptr = g_W + (size_t)bslot*524288 + (size_t)bcol*1024;

    float acc[2][4][4];
    #pragma unroll
    for (int a=0;a<2;a++)
      #pragma unroll
      for (int b=0;b<4;b++)
        #pragma unroll
        for (int c=0;c<4;c++) acc[a][b][c]=0.f;

    auto LOAD = [&](int s, int kt){
        // A (hi+lo)
        if (kt < 512 || ch0 == nullptr){
            const hlf* ph = (kt<512)? a0h : a1h;
            const hlf* pl = (kt<512)? a0l : a1l;
            int kl = kt & 511;
            #pragma unroll
            for (int j=0;j<2;j++){
                int c = cb+j;
                CPA(sb + (uint32_t)(s*A_ST +        row*AW + c*4)*4, ph + kl + c*8);
                CPA(sb + (uint32_t)(s*A_ST + 4608 + row*AW + c*4)*4, pl + kl + c*8);
            }
        } else {
            int kl = kt - 512;
            #pragma unroll
            for (int j=0;j<2;j++){
                int k = kl + (cb+j)*8;
                float4 x0 = *(const float4*)(ch0+k);
                float4 x1 = *(const float4*)(ch0+k+4);
                float4 y0 = *(const float4*)(ch1+k);
                float4 y1 = *(const float4*)(ch1+k+4);
                float s0=x0.x+y0.x, s1=x0.y+y0.y, s2=x0.z+y0.z, s3=x0.w+y0.w;
                float s4=x1.x+y1.x, s5=x1.y+y1.y, s6=x1.z+y1.z, s7=x1.w+y1.w;
                hlf h0,l0,h1,l1,h2,l2,h3,l3,h4,l4,h5,l5,h6,l6,h7,l7;
                split1(s0,h0,l0); split1(s1,h1,l1); split1(s2,h2,l2); split1(s3,h3,l3);
                split1(s4,h4,l4); split1(s5,h5,l5); split1(s6,h6,l6); split1(s7,h7,l7);
                int idx = s*A_ST + row*AW + (cb+j)*4;
                smx[idx+0]=pack2(h0,h1); smx[idx+1]=pack2(h2,h3);
                smx[idx+2]=pack2(h4,h5); smx[idx+3]=pack2(h6,h7);
                smx[idx+4608+0]=pack2(l0,l1); smx[idx+4608+1]=pack2(l2,l3);
                smx[idx+4608+2]=pack2(l4,l5); smx[idx+4608+3]=pack2(l6,l7);
            }
        }
        // B
        #pragma unroll
        for (int j=0;j<2;j++){
            int c = cb+j;
            CPA(sb + (uint32_t)(B_OFF + s*B_ST + row*AW + c*4)*4, bptr + kt + c*8);
        }
    };

    const int L   = tid & 31;
    const int wid = tid >> 5;
    const int wm  = (wid >> 2) << 5;   // 0,32,64,96
    const int wn  = (wid &  3) << 5;   // 0,32,64,96 (logical cols)

    auto COMP = [&](int s){
        #pragma unroll
        for (int ks=0; ks<4; ks++){
            uint32_t af[2][2][4];
            #pragma unroll
            for (int p=0;p<2;p++)
              #pragma unroll
              for (int mt=0;mt<2;mt++){
                  uint32_t ad = sb + (uint32_t)(s*A_ST + p*4608 + (wm + mt*16 + (L&15))*AW)*4
                                   + ((L>>4)<<4) + (ks<<5);
                  LDSM4(af[p][mt][0],af[p][mt][1],af[p][mt][2],af[p][mt][3], ad);
              }
            uint32_t bfr[4][2];
            #pragma unroll
            for (int tp=0;tp<2;tp++){
                int n = wn + tp*16 + (L&7) + ((L>>4)<<3);
                uint32_t bd = sb + (uint32_t)(B_OFF + s*B_ST + n*AW)*4
                                 + (((L>>3)&1)<<4) + (ks<<5);
                uint32_t r0,r1,r2,r3;
                LDSM4(r0,r1,r2,r3,bd);
                bfr[tp*2  ][0]=r0; bfr[tp*2  ][1]=r1;
                bfr[tp*2+1][0]=r2; bfr[tp*2+1][1]=r3;
            }
            #pragma unroll
            for (int p=0;p<2;p++)
              #pragma unroll
              for (int mt=0;mt<2;mt++)
                #pragma unroll
                for (int nt=0;nt<4;nt++)
                    MMA_F16(acc[mt][nt], af[p][mt], bfr[nt]);
        }
    };

    const int niter = kend >> 6;
    LOAD(0,0); CPC();
    for (int it=0; it<niter; ++it){
        if (it+1 < niter){ LOAD((it+1)&1, (it+1)<<6); CPC(); CPW1(); }
        else             { CPW0(); }
        __syncthreads();
        COMP(it & 1);
        __syncthreads();
    }

    // ---------------- epilogue ----------------
    if (NG == 2){
        // stage 1: exchange pre-activations via smem
        float* Sf = reinterpret_cast<float*>(smx);
        #pragma unroll
        for (int mt=0;mt<2;mt++)
          #pragma unroll
          for (int e2=0;e2<2;e2++){
              int rl = wm + mt*16 + (L>>2) + e2*8;
              #pragma unroll
              for (int nt=0;nt<4;nt++){
                  int cl = wn + nt*8 + ((L&3)<<1);
                  Sf[rl*SP + cl]   = acc[mt][nt][e2*2];
                  Sf[rl*SP + cl+1] = acc[mt][nt][e2*2+1];
              }
          }
        __syncthreads();
        // stage 2: combine gates; thread owns 1 row x 16 cols
        int rl = tid >> 2;
        int r = m0 + rl;
        if (r < M){
            int tree = r >> lg, pos = r & ((1<<lg)-1);
            int cg0 = (tid & 3) << 4;
            const float* Zr = Sf + rl*SP;
            if (epi == 0){
                size_t o = (size_t)(tree*NPT + e_fst + pos)*HDIM + n0 + cg0;
                #pragma unroll
                for (int q=0;q<16;q+=4){
                    float4 vz = *(const float4*)(Zr + cg0 + q);
                    float4 vt = *(const float4*)(Zr + 64 + cg0 + q);
                    float h0 = (1.f - sigf(vz.x))*tanhf(vt.x);
                    float h1 = (1.f - sigf(vz.y))*tanhf(vt.y);
                    float h2 = (1.f - sigf(vz.z))*tanhf(vt.z);
                    float h3 = (1.f - sigf(vz.w))*tanhf(vt.w);
                    *(float4*)(g_h + o + q) = make_float4(h0,h1,h2,h3);
                    st_split4(&g_hsp[0][o+q], &g_hsp[1][o+q], h0,h1,h2,h3);
                }
            } else {   // epi 1 / 2
                int col0 = n0 + cg0;
                size_t om = (size_t)r*HDIM + col0;
                size_t oc = (epi==1)
                    ? (size_t)(tree*NPT + e_sst + (pos<<1))*HDIM + col0
                    : (size_t)(tree*NPT + e_fst + (pos>>1))*HDIM + col0;
                #pragma unroll
                for (int q=0;q<16;q+=4){
                    float4 vz = *(const float4*)(Zr + cg0 + q);
                    float4 vr = *(const float4*)(Zr + 64 + cg0 + q);
                    float4 b0 = *(const float4*)(bias0 + col0 + q);
                    float4 b1 = *(const float4*)(bias1 + col0 + q);
                    float4 hs;
                    if (epi==1){
                        float4 c0 = *(const float4*)(g_h + oc + q);
                        float4 c1 = *(const float4*)(g_h + oc + HDIM + q);
                        hs = make_float4(c0.x+c1.x, c0.y+c1.y, c0.z+c1.z, c0.w+c1.w);
                    } else {
                        hs = *(const float4*)(g_hd + oc + q);
                    }
                    float4 zz = make_float4(sigf(vz.x+b0.x), sigf(vz.y+b0.y),
                                            sigf(vz.z+b0.z), sigf(vz.w+b0.w));
                    float r0 = sigf(vr.x+b1.x), r1 = sigf(vr.y+b1.y);
                    float r2 = sigf(vr.z+b1.z), r3 = sigf(vr.w+b1.w);
                    *(float4*)(g_z + om + q) = zz;
                    st_split4(&g_V[0][om+q], &g_V[1][om+q],
                              r0*hs.x, r1*hs.y, r2*hs.z, r3*hs.w);
                }
            }
        }
    } else {
        // NG==1: direct per-fragment epilogue (epi 3/4/5)
        #pragma unroll
        for (int mt=0;mt<2;mt++)
        #pragma unroll
        for (int e2=0;e2<2;e2++){
            int r = m0 + wm + mt*16 + (L>>2) + e2*8;
            if (r >= M) continue;
            int tree = r >> lg, pos = r & ((1<<lg)-1);
            #pragma unroll
            for (int nt=0;nt<4;nt++){
                int c = n0 + wn + nt*8 + ((L&3)<<1);
                float v0 = acc[mt][nt][e2*2+0];
                float v1 = acc[mt][nt][e2*2+1];
                if (epi == 5){
                    outp[(size_t)r*HDIM + c]   = v0 + bias0[c]   + bias1[c];
                    outp[(size_t)r*HDIM + c+1] = v1 + bias0[c+1] + bias1[c+1];
                } else {   // epi 3 / 4
                    float cand0 = tanhf(v0), cand1 = tanhf(v1);
                    size_t om = (size_t)r*HDIM + c;
                    float z0 = g_z[om], z1 = g_z[om+1];
                    float hs0, hs1; int node;
                    if (epi == 3){
                        size_t oc = (size_t)(tree*NPT + e_sst + (pos<<1))*HDIM + c;
                        hs0 = g_h[oc]   + g_h[oc+HDIM];
                        hs1 = g_h[oc+1] + g_h[oc+1+HDIM];
                        node = tree*NPT + e_fst + pos;
                    } else {
                        size_t of = (size_t)(tree*NPT + e_fst + (pos>>1))*HDIM + c;
                        hs0 = g_hd[of]; hs1 = g_hd[of+1];
                        node = tree*NPT + e_sst + pos;
                    }
                    float h0 = z0*hs0 + (1.f-z0)*cand0;
                    float h1 = z1*hs1 + (1.f-z1)*cand1;
                    size_t o = (size_t)node*HDIM + c;
                    if (epi == 3){
                        g_h[o]=h0; g_h[o+1]=h1;
                        st_split2(&g_hsp[0][o], &g_hsp[1][o], h0, h1);
                    } else {
                        g_hd[o]=h0; g_hd[o+1]=h1;
                        st_split2(&g_hdp[0][o], &g_hdp[1][o], h0, h1);
                    }
                }
            }
        }
    }
}

// ---------------- host orchestration ----------------
extern "C" void kernel_launch(void* const* d_in, const int* in_sizes, int n_in,
                              void* d_out, int out_size)
{
    (void)in_sizes; (void)n_in; (void)out_size;
    const float* feat = (const float*)d_in[0];
    const float* Wh   = (const float*)d_in[1];
    const float* Wz   = (const float*)d_in[2];
    const float* Wr   = (const float*)d_in[3];
    const float* Uh   = (const float*)d_in[4];
    const float* Uz   = (const float*)d_in[5];
    const float* bUz  = (const float*)d_in[6];
    const float* Ur   = (const float*)d_in[7];
    const float* bUr  = (const float*)d_in[8];
    const float* Whd  = (const float*)d_in[9];
    const float* Wzd  = (const float*)d_in[10];
    const float* Wrd  = (const float*)d_in[11];
    const float* Uhd  = (const float*)d_in[12];
    const float* Uzd  = (const float*)d_in[13];
    const float* bUzd = (const float*)d_in[14];
    const float* Urd  = (const float*)d_in[15];
    const float* bUrd = (const float*)d_in[16];
    const float* W1   = (const float*)d_in[17];
    const float* b1   = (const float*)d_in[18];
    const float* W2   = (const float*)d_in[19];
    const float* b2   = (const float*)d_in[20];
    float* out = (float*)d_out;

    cudaFuncSetAttribute(mma_g<1>, cudaFuncAttributeMaxDynamicSharedMemorySize, SMEMB);
    cudaFuncSetAttribute(mma_g<2>, cudaFuncAttributeMaxDynamicSharedMemorySize, SMEMB);

    // slots: 0 [Wz|Uz]  1 [Wr|Ur]  2 [Wh|Uh]  3 [Wzd|Uzd]  4 [Wrd|Urd]  5 [Whd|Uhd]  6 [W1|W2]
    split_w<<<dim3(2048,7),256>>>(Wz,Uz, Wr,Ur, Wh,Uh, Wzd,Uzd, Wrd,Urd, Whd,Uhd, W1,W2);
    split_feat<<<65520,256>>>(feat);

    static const int LS[12] = {0,2048,3072,3584,3840,3968,4032,4064,4080,4088,4092,4094};
    static const int LG[12] = {11,10,9,8,7,6,5,4,3,2,1,0};

    // ---- leaves: z = sig(X@Wz), th = X@Wh -> h ----
    mma_g<2><<<dim3(8,128),512,SMEMB>>>(512, 0,0,0, 0,0,0, 0,2,
                                        nullptr,nullptr, NB*2048, 11, 0, 0, 0, nullptr);

    // ---- bottom-up ----
    for (int l=0; l<11; l++){
        int lgf = LG[l+1];
        int M   = NB << lgf;
        int sst = LS[l], fst = LS[l+1];
        int mb  = (M+127)/128;
        // z,r: [X_fa | sum(children h)] @ [Wz;Uz],[Wr;Ur]
        mma_g<2><<<dim3(8,mb),512,SMEMB>>>(1024, 0,0,fst, 0,1,sst, 0,1,
                                           bUz,bUr, M, lgf, 1, sst, fst, nullptr);
        // th: [X_fa | V] @ [Wh;Uh] -> h
        mma_g<1><<<dim3(4,mb),512,SMEMB>>>(1024, 0,0,fst, 3,3,0, 2,2,
                                           nullptr,nullptr, M, lgf, 3, sst, fst, nullptr);
    }

    root_copy<<<16,256>>>();

    // ---- top-down ----
    for (int l=10; l>=0; l--){
        int lgs = LG[l];
        int M   = NB << lgs;
        int sst = LS[l], fst = LS[l+1];
        int mb  = (M+127)/128;
        // zd,rd: [X_son | hd_father] @ [Wzd;Uzd],[Wrd;Urd]
        mma_g<2><<<dim3(8,mb),512,SMEMB>>>(1024, 0,0,sst, 2,2,fst, 3,4,
                                           bUzd,bUrd, M, lgs, 2, sst, fst, nullptr);
        // th: [X_son | V] @ [Whd;Uhd] -> hd
        mma_g<1><<<dim3(4,mb),512,SMEMB>>>(1024, 0,0,sst, 3,3,0, 5,5,
                                           nullptr,nullptr, M, lgs, 4, sst, fst, nullptr);
    }

    // ---- output: [h|hd] @ [W1;W2] + b1 + b2 ----
    mma_g<1><<<dim3(4,256),512,SMEMB>>>(1024, 1,3,0, 2,3,0, 6,6,
                                        b1,b2, NTOT, 1, 5, 0, 0, out);
}